// round 17
// baseline (speedup 1.0000x reference)
#include <cuda_runtime.h>
#include <cstdint>

#define TS 4096
#define NH 16
#define HD 128
#define NP 512
#define BM 128
#define BN 64
#define NT 256            // 8 warps
#define SCALE 0.08838834764831845f
#define HSC 21.166666667f            // 127/6
#define INV_HSC 0.047244094488f      // 6/127
#define C1 1.972835e-4f              // SCALE/HSC^2
#define C2 1.5412773e-6f             // C1/128

// ---- device scratch ----
// K int8 planes: [blk 3][h 16][j 512][dgroup 32] (4 int8 per u32)
__device__ uint32_t g_kih[3*16*512*32];
__device__ uint32_t g_kil[3*16*512*32];
// Q int8 planes: [s 4096][h 16][dgroup 32]
__device__ uint32_t g_qih[4096*16*32];
__device__ uint32_t g_qil[4096*16*32];
// V^T fp16 packed key-pairs: [blk 3][h 16][d 128][jpair 256]
__device__ uint32_t g_vtf[3*16*128*256];

static __device__ __forceinline__ uint32_t s2u(const void* p){
  uint32_t a; asm("{ .reg .u64 t; cvta.to.shared.u64 t, %1; cvt.u32.u64 %0, t; }" : "=r"(a) : "l"(p)); return a;
}
static __device__ __forceinline__ uint16_t f2h(float x){
  uint16_t r; asm("cvt.rn.f16.f32 %0, %1;" : "=h"(r) : "f"(x)); return r;
}
static __device__ __forceinline__ uint32_t packh(float x0, float x1){
  uint32_t r; asm("cvt.rn.f16x2.f32 %0, %1, %2;" : "=r"(r) : "f"(x1), "f"(x0)); return r;
}
// quantize one float -> (hi int8, lo int8)
static __device__ __forceinline__ void q8(float x, int& hi, int& lo){
  float xh = rintf(fminf(fmaxf(x*HSC, -127.f), 127.f));
  float r  = x - xh*INV_HSC;
  float xl = rintf(r*(HSC*128.f));
  hi = (int)xh; lo = (int)xl;
}
static __device__ __forceinline__ uint32_t pack4(int b0, int b1, int b2, int b3){
  return (uint32_t)(b0 & 0xff) | ((uint32_t)(b1 & 0xff) << 8)
       | ((uint32_t)(b2 & 0xff) << 16) | ((uint32_t)(b3 & 0xff) << 24);
}
static __device__ __forceinline__ void mma_s8(int* d, const uint32_t* a, const uint32_t* b){
  asm volatile(
    "mma.sync.aligned.m16n8k32.row.col.s32.s8.s8.s32 "
    "{%0,%1,%2,%3}, {%4,%5,%6,%7}, {%8,%9}, {%0,%1,%2,%3};"
    : "+r"(d[0]), "+r"(d[1]), "+r"(d[2]), "+r"(d[3])
    : "r"(a[0]), "r"(a[1]), "r"(a[2]), "r"(a[3]), "r"(b[0]), "r"(b[1]));
}
static __device__ __forceinline__ void mma_f16(float* d, const uint32_t* a, const uint32_t* b){
  asm volatile(
    "mma.sync.aligned.m16n8k16.row.col.f32.f16.f16.f32 "
    "{%0,%1,%2,%3}, {%4,%5,%6,%7}, {%8,%9}, {%0,%1,%2,%3};"
    : "+f"(d[0]), "+f"(d[1]), "+f"(d[2]), "+f"(d[3])
    : "r"(a[0]), "r"(a[1]), "r"(a[2]), "r"(a[3]), "r"(b[0]), "r"(b[1]));
}
static __device__ __forceinline__ void ldsm4(uint32_t& r0, uint32_t& r1, uint32_t& r2, uint32_t& r3, uint32_t addr){
  asm volatile("ldmatrix.sync.aligned.m8n8.x4.shared.b16 {%0,%1,%2,%3}, [%4];"
               : "=r"(r0), "=r"(r1), "=r"(r2), "=r"(r3) : "r"(addr));
}
static __device__ __forceinline__ void cpa16(uint32_t dst, const void* src){
  asm volatile("cp.async.cg.shared.global [%0], [%1], 16;" :: "r"(dst), "l"(src) : "memory");
}
#define CP_COMMIT() asm volatile("cp.async.commit_group;" ::: "memory")
#define CP_WAIT0()  asm volatile("cp.async.wait_group 0;" ::: "memory")

// ================= pre-pass kernels =================
// K -> int8 hi/lo planes (thread = 4 dims of one key)
__global__ void prep_k(const float* __restrict__ k, const float* __restrict__ rk){
  int g = blockIdx.x * blockDim.x + threadIdx.x;       // 3*16*512*32
  int dg = g & 31; int r = g >> 5;
  int j = r & 511; r >>= 9;
  int h = r & 15;  int blk = r >> 4;
  const float* src = (blk == 0)
    ? (k  + ((size_t)j*NH + h)*HD + dg*4)
    : (rk + (((size_t)(blk-1)*NP + j)*NH + h)*HD + dg*4);
  float4 x = *(const float4*)src;
  int h0,l0,h1,l1,h2,l2,h3,l3;
  q8(x.x,h0,l0); q8(x.y,h1,l1); q8(x.z,h2,l2); q8(x.w,h3,l3);
  g_kih[g] = pack4(h0,h1,h2,h3);
  g_kil[g] = pack4(l0,l1,l2,l3);
}
// Q -> int8 hi/lo planes
__global__ void prep_q(const float* __restrict__ q){
  int g = blockIdx.x * blockDim.x + threadIdx.x;       // 4096*16*32
  float4 x = *(const float4*)(q + (size_t)g*4);
  int h0,l0,h1,l1,h2,l2,h3,l3;
  q8(x.x,h0,l0); q8(x.y,h1,l1); q8(x.z,h2,l2); q8(x.w,h3,l3);
  g_qih[g] = pack4(h0,h1,h2,h3);
  g_qil[g] = pack4(l0,l1,l2,l3);
}
// V -> fp16 plane transposed (verified R12/R16)
__global__ void prep_v(const float* __restrict__ v, const float* __restrict__ rv){
  __shared__ uint16_t sh[128][66];
  int jt  = blockIdx.x;
  int h   = blockIdx.y;
  int blk = blockIdx.z;
  int tid = threadIdx.x;
  const float* src = (blk == 0) ? v : (rv + (size_t)(blk-1)*NP*NH*HD);
  #pragma unroll
  for (int i = 0; i < 8; i++){
    int f = i*256 + tid;
    int j = f >> 5; int d0 = (f & 31) << 2;
    float4 x = *(const float4*)(src + ((size_t)(jt*64 + j)*NH + h)*HD + d0);
    sh[d0+0][j] = f2h(x.x);
    sh[d0+1][j] = f2h(x.y);
    sh[d0+2][j] = f2h(x.z);
    sh[d0+3][j] = f2h(x.w);
  }
  __syncthreads();
  size_t base = ((size_t)(blk*NH + h)*128)*256 + jt*32;
  #pragma unroll
  for (int i = 0; i < 16; i++){
    int u = i*256 + tid;
    int d = u >> 5; int jp = u & 31;
    g_vtf[base + (size_t)d*256 + jp] = ((uint32_t)sh[d][jp*2+1] << 16) | sh[d][jp*2];
  }
}

// ================= main kernel =================
// smem (u32), all rows pitch 36 u32 (144B, conflict-free for ldmatrix)
#define QIH_OFF 0                          // 128x36
#define QIL_OFF (QIH_OFF + 128*36)         // 4608
#define KIH_OFF (QIL_OFF + 128*36)         // 9216, + buf*64*36
#define KIL_OFF (KIH_OFF + 2*64*36)        // 13824, + buf*64*36
#define VF_OFF  (KIL_OFF + 2*64*36)        // 18432, + buf*128*36
#define SMEM_U32 (VF_OFF + 2*128*36)       // 27648 u32 = 110592 B

static __device__ __forceinline__ void load_chunk(uint32_t sb, int t, int h, int buf, int tid){
  int blk = (t < 8) ? 0 : (1 + ((t - 8) >> 3));
  int j0  = ((t < 8) ? t : ((t - 8) & 7)) * BN;
  const uint32_t* kh = g_kih + ((size_t)(blk*NH + h)*512 + j0)*32;
  const uint32_t* kl = g_kil + ((size_t)(blk*NH + h)*512 + j0)*32;
  const uint32_t* vf = g_vtf + ((size_t)(blk*NH + h)*128)*256 + (j0 >> 1);
  uint32_t kdh = sb + (KIH_OFF + buf*64*36)*4u;
  uint32_t kdl = sb + (KIL_OFF + buf*64*36)*4u;
  uint32_t vdf = sb + (VF_OFF  + buf*128*36)*4u;
  // K: 64 rows x 8 segs = 512 per plane
  #pragma unroll
  for (int i = 0; i < 2; i++){
    int f = i*NT + tid;
    int row = f >> 3, seg = f & 7;
    cpa16(kdh + (uint32_t)(row*36 + seg*4)*4u, kh + (size_t)row*32 + seg*4);
    cpa16(kdl + (uint32_t)(row*36 + seg*4)*4u, kl + (size_t)row*32 + seg*4);
  }
  // V: 128 rows x 8 segs = 1024
  #pragma unroll
  for (int i = 0; i < 4; i++){
    int f = i*NT + tid;
    int vrow = f >> 3, vseg = f & 7;
    cpa16(vdf + (uint32_t)(vrow*36 + vseg*4)*4u, vf + (size_t)vrow*256 + vseg*4);
  }
}

// One 64-key chunk: QK int8 3-term (2 halves of 32 keys) -> exp -> PV fp16.
static __device__ __forceinline__ void do_chunk(
    uint32_t sb, int t, int h, int tid,
    uint32_t qa_h, uint32_t qa_l, uint32_t kb_off, uint32_t vb_off,
    float (&o)[16][4], int a0, int a1, float& su0t, float& su1t)
{
  CP_WAIT0();
  __syncthreads();
  if (t + 1 < 24){
    load_chunk(sb, t+1, h, (t+1)&1, tid);
    CP_COMMIT();
  }

  const uint32_t kh_base = sb + (uint32_t)(KIH_OFF + (t&1)*64*36)*4u + kb_off;
  const uint32_t kl_base = sb + (uint32_t)(KIL_OFF + (t&1)*64*36)*4u + kb_off;
  const uint32_t vf_base = sb + (uint32_t)(VF_OFF  + (t&1)*128*36)*4u + vb_off;

  // ---- QK^T int8: S = [I1 + (I2+I3)/128] * C1, processed in two 32-key halves
  float sf[8][4];
  #pragma unroll
  for (int half = 0; half < 2; half++){
    int ac1[4][4], ac2[4][4];
    #pragma unroll
    for (int j = 0; j < 4; j++)
      #pragma unroll
      for (int e = 0; e < 4; e++){ ac1[j][e] = 0; ac2[j][e] = 0; }

    #pragma unroll
    for (int ks = 0; ks < 4; ks++){
      uint32_t ah[4], al[4];
      ldsm4(ah[0], ah[1], ah[2], ah[3], qa_h + ks*32u);
      ldsm4(al[0], al[1], al[2], al[3], qa_l + ks*32u);
      #pragma unroll
      for (int g = 0; g < 2; g++){
        uint32_t bh[4], bl[4];
        uint32_t koff = (uint32_t)((half*32 + g*16)*144) + ks*32u;
        ldsm4(bh[0], bh[1], bh[2], bh[3], kh_base + koff);
        ldsm4(bl[0], bl[1], bl[2], bl[3], kl_base + koff);
        mma_s8(ac1[2*g],   ah, &bh[0]);
        mma_s8(ac1[2*g+1], ah, &bh[2]);
        mma_s8(ac2[2*g],   ah, &bl[0]);
        mma_s8(ac2[2*g+1], ah, &bl[2]);
        mma_s8(ac2[2*g],   al, &bh[0]);
        mma_s8(ac2[2*g+1], al, &bh[2]);
      }
    }
    #pragma unroll
    for (int j = 0; j < 4; j++)
      #pragma unroll
      for (int e = 0; e < 4; e++)
        sf[half*4 + j][e] = fmaf((float)ac2[j][e], C2, (float)ac1[j][e]*C1);
  }

  // ---- exp (SCALE already folded into C1/C2), pack P fp16
  uint32_t pa[8], pb[8];
  float su0 = 0.f, su1 = 0.f;
  #pragma unroll
  for (int n = 0; n < 8; n++){
    float p0 = a0 ? __expf(sf[n][0]) : 0.f;
    float p1 = a0 ? __expf(sf[n][1]) : 0.f;
    float p2 = a1 ? __expf(sf[n][2]) : 0.f;
    float p3 = a1 ? __expf(sf[n][3]) : 0.f;
    su0 += p0 + p1; su1 += p2 + p3;
    pa[n] = packh(p0, p1);
    pb[n] = packh(p2, p3);
  }
  su0t += su0; su1t += su1;

  // ---- P@V (fp16): 4 k-steps x 16 n-tiles
  #pragma unroll
  for (int s = 0; s < 4; s++){
    uint32_t ph[4] = { pa[2*s], pb[2*s], pa[2*s+1], pb[2*s+1] };
    #pragma unroll
    for (int g = 0; g < 2; g++){
      uint32_t B[4][4];
      #pragma unroll
      for (int i = 0; i < 4; i++){
        int np = g*4 + i;
        ldsm4(B[i][0], B[i][1], B[i][2], B[i][3], vf_base + (uint32_t)(np*2*8*36)*4u + s*32u);
      }
      #pragma unroll
      for (int i = 0; i < 4; i++){
        int np = g*4 + i;
        mma_f16(o[2*np],   ph, &B[i][0]);
        mma_f16(o[2*np+1], ph, &B[i][2]);
      }
    }
  }
}

__global__ __launch_bounds__(NT, 1)
void regional_attn_main(const int* __restrict__ masks, float* __restrict__ out)
{
  extern __shared__ uint32_t smu[];
  const uint32_t sb = s2u(smu);
  const int tid  = threadIdx.x;
  const int lane = tid & 31;
  const int wid  = tid >> 5;
  const int quad = lane >> 2;
  const int qt   = lane & 3;
  const int h = blockIdx.y;
  const int sBase = blockIdx.x * BM;

  // Q prologue: 128 rows x 8 segs per plane
  {
    const uint32_t* qh = g_qih + ((size_t)sBase*NH + h)*32;
    const uint32_t* ql = g_qil + ((size_t)sBase*NH + h)*32;
    #pragma unroll
    for (int i = 0; i < 4; i++){
      int f = i*NT + tid;
      int row = f >> 3, seg = f & 7;
      cpa16(sb + (uint32_t)(QIH_OFF + row*36 + seg*4)*4u, qh + (size_t)row*NH*32 + seg*4);
      cpa16(sb + (uint32_t)(QIL_OFF + row*36 + seg*4)*4u, ql + (size_t)row*NH*32 + seg*4);
    }
  }
  load_chunk(sb, 0, h, 0, tid);
  CP_COMMIT();

  // ldmatrix per-lane addressing (pitch 144B, int8 rows)
  const uint32_t lrow = lane & 7;
  const uint32_t lm   = (uint32_t)lane >> 3;
  const uint32_t qa_h = sb + (uint32_t)(QIH_OFF + (wid*16 + (int)lrow + (int)((lm&1)*8))*36)*4u + (lm>>1)*16u;
  const uint32_t qa_l = qa_h + (uint32_t)(128*36)*4u;   // QIL_OFF - QIH_OFF
  const uint32_t kb_off = (uint32_t)(((lm>>1)*8 + lrow)*144) + (lm&1)*16u;
  const uint32_t vb_off = (uint32_t)((((lm>>1)*8 + lrow)*36 + (lm&1)*4))*4u;

  const int s0 = sBase + wid*16 + quad;
  const int s1 = s0 + 8;
  const int m0r0 = (masks[s0]      != 0), m0r1 = (masks[s1]      != 0);
  const int m1r0 = (masks[TS + s0] != 0), m1r1 = (masks[TS + s1] != 0);
  const int anyr0 = m0r0 | m1r0;
  const int anyr1 = m0r1 | m1r1;
  const unsigned FULL = 0xffffffffu;

  float o[16][4];
  #pragma unroll
  for (int n = 0; n < 16; n++)
    #pragma unroll
    for (int e = 0; e < 4; e++) o[n][e] = 0.f;

  float* o0p = out + (size_t)s0*(size_t)(NH*HD) + (size_t)h*HD + 2*qt;
  float* o1p = out + (size_t)s1*(size_t)(NH*HD) + (size_t)h*HD + 2*qt;

  // ---- base pass (chunks 0..7)
  {
    float l0 = 0.f, l1 = 0.f;
    #pragma unroll 1
    for (int t = 0; t < 8; t++)
      do_chunk(sb, t, h, tid, qa_h, qa_l, kb_off, vb_off, o, 1, 1, l0, l1);

    l0 += __shfl_xor_sync(FULL, l0, 1, 4); l0 += __shfl_xor_sync(FULL, l0, 2, 4);
    l1 += __shfl_xor_sync(FULL, l1, 1, 4); l1 += __shfl_xor_sync(FULL, l1, 2, 4);
    const float w0 = (anyr0 ? 0.5f : 1.0f) / l0;
    const float w1 = (anyr1 ? 0.5f : 1.0f) / l1;
    #pragma unroll
    for (int n = 0; n < 16; n++){
      *(float2*)(o0p + n*8) = make_float2(o[n][0]*w0, o[n][1]*w0);
      *(float2*)(o1p + n*8) = make_float2(o[n][2]*w1, o[n][3]*w1);
      o[n][0] = 0.f; o[n][1] = 0.f; o[n][2] = 0.f; o[n][3] = 0.f;
    }
  }

  // ---- regional pass (chunks 8..23)
  {
    float l0 = 0.f, l1 = 0.f;
    #pragma unroll 1
    for (int t = 8; t < 16; t++)
      do_chunk(sb, t, h, tid, qa_h, qa_l, kb_off, vb_off, o, m0r0, m0r1, l0, l1);
    #pragma unroll 1
    for (int t = 16; t < 24; t++)
      do_chunk(sb, t, h, tid, qa_h, qa_l, kb_off, vb_off, o, m1r0, m1r1, l0, l1);

    l0 += __shfl_xor_sync(FULL, l0, 1, 4); l0 += __shfl_xor_sync(FULL, l0, 2, 4);
    l1 += __shfl_xor_sync(FULL, l1, 1, 4); l1 += __shfl_xor_sync(FULL, l1, 2, 4);
    const float w0 = anyr0 ? (0.5f / l0) : 0.f;
    const float w1 = anyr1 ? (0.5f / l1) : 0.f;
    #pragma unroll
    for (int n = 0; n < 16; n++){
      float2 a = *(const float2*)(o0p + n*8);
      float2 b = *(const float2*)(o1p + n*8);
      a.x += o[n][0]*w0; a.y += o[n][1]*w0;
      b.x += o[n][2]*w1; b.y += o[n][3]*w1;
      *(float2*)(o0p + n*8) = a;
      *(float2*)(o1p + n*8) = b;
    }
  }
}

extern "C" void kernel_launch(void* const* d_in, const int* in_sizes, int n_in,
                              void* d_out, int out_size)
{
  const float* q     = (const float*)d_in[0];
  const float* k     = (const float*)d_in[1];
  const float* v     = (const float*)d_in[2];
  const float* rk    = (const float*)d_in[3];
  const float* rv    = (const float*)d_in[4];
  const int*   masks = (const int*)d_in[5];
  float* out = (float*)d_out;

  prep_k<<<3*16*512*32/256, 256>>>(k, rk);
  prep_q<<<4096*16*32/256, 256>>>(q);
  { dim3 g(8, 16, 3); prep_v<<<g, 256>>>(v, rv); }

  const int smem = SMEM_U32 * 4;   // 110592
  cudaFuncSetAttribute(regional_attn_main,
                       cudaFuncAttributeMaxDynamicSharedMemorySize, smem);
  dim3 grid(TS / BM, NH);   // (32, 16)
  regional_attn_main<<<grid, NT, smem>>>(masks, out);
}